// round 6
// baseline (speedup 1.0000x reference)
#include <cuda_runtime.h>
#include <cstdint>

// Problem constants (match reference)
#define T_SLICES 8
#define N_SUB    20000
#define M_SUB    5000
#define H        128
#define NNZ_G    200000
#define NNZ_E    100000
#define ITEM_NUM 40000
#define USER_NUM 10000

// Output layout:
//   rows [0, 50000)        = user_buf  (0..9999 user_base, then T*5000 edge rows)
//   rows [50000, 250000)   = item_buf  (50000..89999 item_base, then T*20000 x rows)

// Scratch (no allocations allowed -> __device__ globals)
__device__ float g_x[N_SUB * H];   // 10 MB
__device__ float g_y[N_SUB * H];   // 10 MB

// ---------------------------------------------------------------------------
// Gate kernel: per block, 32 nodes.
//   a0 = item_base[rev_i[n]], a1 = item_dy_table[rev_latest_i[n]]
//   s_k = sigmoid(a_k @ W_gate + b_gate);  x = s0*a0 + s1*a1
// smem: W (128x128) + a0 tile (32x128) + a1 tile (32x128) = 96 KB
// threads 256: warp-uniform A broadcasts, float4 W reads -> FFMA-bound.
// ---------------------------------------------------------------------------
__global__ void gate_kernel(const float* __restrict__ item_base,
                            const float* __restrict__ item_dy,
                            const float* __restrict__ W,
                            const float* __restrict__ b,
                            const int*   __restrict__ rev,
                            const int*   __restrict__ rev_dy,
                            float*       __restrict__ out)
{
    extern __shared__ float sm[];
    float* sW  = sm;                 // 128*128
    float* sA0 = sm + 128 * 128;     // 32*128
    float* sA1 = sA0 + 32 * 128;     // 32*128

    const int tid = threadIdx.x;     // 256 threads
    const int row0_blk = blockIdx.x * 32;

    // Load W (row-major [h][d]) via float4
    {
        float4*       dst = (float4*)sW;
        const float4* src = (const float4*)W;
        #pragma unroll
        for (int i = tid; i < 128 * 128 / 4; i += 256) dst[i] = src[i];
    }
    // Gather A tiles: 32 rows, 8 threads/row, 4 float4 each
    {
        const int r = tid >> 3;          // 0..31
        const int p = tid & 7;           // 0..7
        const int n = row0_blk + r;
        const float4* s0 = (const float4*)(item_base + (size_t)rev[n]    * H);
        const float4* s1 = (const float4*)(item_dy   + (size_t)rev_dy[n] * H);
        float4* d0 = (float4*)(sA0 + r * H);
        float4* d1 = (float4*)(sA1 + r * H);
        #pragma unroll
        for (int j = 0; j < 4; j++) {
            d0[p + j * 8] = s0[p + j * 8];
            d1[p + j * 8] = s1[p + j * 8];
        }
    }
    __syncthreads();

    const int ty = tid >> 5;   // 0..7 -> rows
    const int tx = tid & 31;   // 0..31 -> cols
    const int r0 = ty * 4;
    const int c0 = tx * 4;

    float acc0[4][4];
    float acc1[4][4];
    #pragma unroll
    for (int i = 0; i < 4; i++)
        #pragma unroll
        for (int j = 0; j < 4; j++) { acc0[i][j] = 0.f; acc1[i][j] = 0.f; }

    #pragma unroll 4
    for (int k = 0; k < H; k++) {
        const float4 w = *(const float4*)&sW[k * 128 + c0];
        #pragma unroll
        for (int i = 0; i < 4; i++) {
            const float a0 = sA0[(r0 + i) * H + k];   // warp-uniform broadcast
            const float a1 = sA1[(r0 + i) * H + k];
            acc0[i][0] += a0 * w.x; acc0[i][1] += a0 * w.y;
            acc0[i][2] += a0 * w.z; acc0[i][3] += a0 * w.w;
            acc1[i][0] += a1 * w.x; acc1[i][1] += a1 * w.y;
            acc1[i][2] += a1 * w.z; acc1[i][3] += a1 * w.w;
        }
    }

    const float4 bb = *(const float4*)&b[c0];
    #pragma unroll
    for (int i = 0; i < 4; i++) {
        const int n = row0_blk + r0 + i;
        const float4 a0 = *(const float4*)&sA0[(r0 + i) * H + c0];
        const float4 a1 = *(const float4*)&sA1[(r0 + i) * H + c0];
        float4 o;
        {
            float s0 = 1.f / (1.f + __expf(-(acc0[i][0] + bb.x)));
            float s1 = 1.f / (1.f + __expf(-(acc1[i][0] + bb.x)));
            o.x = s0 * a0.x + s1 * a1.x;
        }
        {
            float s0 = 1.f / (1.f + __expf(-(acc0[i][1] + bb.y)));
            float s1 = 1.f / (1.f + __expf(-(acc1[i][1] + bb.y)));
            o.y = s0 * a0.y + s1 * a1.y;
        }
        {
            float s0 = 1.f / (1.f + __expf(-(acc0[i][2] + bb.z)));
            float s1 = 1.f / (1.f + __expf(-(acc1[i][2] + bb.z)));
            o.z = s0 * a0.z + s1 * a1.z;
        }
        {
            float s0 = 1.f / (1.f + __expf(-(acc0[i][3] + bb.w)));
            float s1 = 1.f / (1.f + __expf(-(acc1[i][3] + bb.w)));
            o.w = s0 * a0.w + s1 * a1.w;
        }
        *(float4*)&out[(size_t)n * H + c0] = o;
    }
}

// ---------------------------------------------------------------------------
// GEMM + bias: out[n,:] = (relu_in ? relu(in[n,:]) : in[n,:]) @ W + b
// Block: 64 rows. smem W + A tile = 96 KB. Thread micro-tile 8x4.
// ---------------------------------------------------------------------------
__global__ void gemm_kernel(const float* __restrict__ in,
                            const float* __restrict__ W,
                            const float* __restrict__ b,
                            float*       __restrict__ out,
                            int relu_in, int n_rows)
{
    extern __shared__ float sm[];
    float* sW = sm;               // 128*128
    float* sA = sm + 128 * 128;   // 64*128

    const int tid  = threadIdx.x;   // 256
    const int row0_blk = blockIdx.x * 64;

    {
        float4*       dst = (float4*)sW;
        const float4* src = (const float4*)W;
        #pragma unroll
        for (int i = tid; i < 128 * 128 / 4; i += 256) dst[i] = src[i];
    }
    {
        const int r = tid >> 2;       // 0..63
        const int p = tid & 3;        // 0..3
        int n = row0_blk + r;
        if (n > n_rows - 1) n = n_rows - 1;   // clamp (stores are guarded)
        const float4* s = (const float4*)(in + (size_t)n * H);
        float4* d = (float4*)(sA + r * H);
        #pragma unroll
        for (int j = 0; j < 8; j++) {
            float4 v = s[p + j * 4];
            if (relu_in) {
                v.x = fmaxf(v.x, 0.f); v.y = fmaxf(v.y, 0.f);
                v.z = fmaxf(v.z, 0.f); v.w = fmaxf(v.w, 0.f);
            }
            d[p + j * 4] = v;
        }
    }
    __syncthreads();

    const int ty = tid >> 5;
    const int tx = tid & 31;
    const int r0 = ty * 8;
    const int c0 = tx * 4;

    float acc[8][4];
    #pragma unroll
    for (int i = 0; i < 8; i++)
        #pragma unroll
        for (int j = 0; j < 4; j++) acc[i][j] = 0.f;

    #pragma unroll 4
    for (int k = 0; k < H; k++) {
        const float4 w = *(const float4*)&sW[k * 128 + c0];
        #pragma unroll
        for (int i = 0; i < 8; i++) {
            const float a = sA[(r0 + i) * H + k];
            acc[i][0] += a * w.x; acc[i][1] += a * w.y;
            acc[i][2] += a * w.z; acc[i][3] += a * w.w;
        }
    }

    const float4 bb = *(const float4*)&b[c0];
    #pragma unroll
    for (int i = 0; i < 8; i++) {
        const int n = row0_blk + r0 + i;
        if (n < n_rows) {
            float4 o;
            o.x = acc[i][0] + bb.x; o.y = acc[i][1] + bb.y;
            o.z = acc[i][2] + bb.z; o.w = acc[i][3] + bb.w;
            *(float4*)&out[(size_t)n * H + c0] = o;
        }
    }
}

// ---------------------------------------------------------------------------
// SpMM (COO): out[rows[e], :] += vals[e] * in[cols[e], :]   (warp per nnz)
// out must be pre-zeroed. Uses red.global.add.v4.f32 (sm_90+).
// ---------------------------------------------------------------------------
__global__ void spmm_kernel(const int*   __restrict__ rows,
                            const int*   __restrict__ cols,
                            const float* __restrict__ vals,
                            int nnz,
                            const float* __restrict__ in,
                            float*       __restrict__ out)
{
    const int lane   = threadIdx.x & 31;
    const int warp   = (blockIdx.x * blockDim.x + threadIdx.x) >> 5;
    const int nwarps = (gridDim.x * blockDim.x) >> 5;

    for (int e = warp; e < nnz; e += nwarps) {
        const int   r = rows[e];
        const int   c = cols[e];
        const float v = vals[e];
        const float4 x = *(const float4*)(in + (size_t)c * H + lane * 4);
        float* p = out + (size_t)r * H + lane * 4;
        asm volatile("red.global.add.v4.f32 [%0], {%1,%2,%3,%4};"
                     :: "l"(p), "f"(x.x * v), "f"(x.y * v), "f"(x.z * v), "f"(x.w * v)
                     : "memory");
    }
}

// relu + copy, float4 grid-stride
__global__ void relu_copy_kernel(const float* __restrict__ in,
                                 float* __restrict__ out, int n4)
{
    int i = blockIdx.x * blockDim.x + threadIdx.x;
    if (i < n4) {
        float4 v = ((const float4*)in)[i];
        v.x = fmaxf(v.x, 0.f); v.y = fmaxf(v.y, 0.f);
        v.z = fmaxf(v.z, 0.f); v.w = fmaxf(v.w, 0.f);
        ((float4*)out)[i] = v;
    }
}

extern "C" void kernel_launch(void* const* d_in, const int* in_sizes, int n_in,
                              void* d_out, int out_size)
{
    const float* item_base = (const float*)d_in[0];
    const float* user_base = (const float*)d_in[1];
    const float* item_dy   = (const float*)d_in[2];
    const float* W_gate    = (const float*)d_in[3];
    const float* b_gate    = (const float*)d_in[4];
    const float* W_hgnn    = (const float*)d_in[5];
    const float* b_hgnn    = (const float*)d_in[6];
    const float* g_vals    = (const float*)d_in[7];
    const float* e_vals    = (const float*)d_in[8];
    const int*   rev_i     = (const int*)d_in[9];
    const int*   rev_li    = (const int*)d_in[10];
    const int*   g_rows    = (const int*)d_in[11];
    const int*   g_cols    = (const int*)d_in[12];
    const int*   e_rows    = (const int*)d_in[13];
    const int*   e_cols    = (const int*)d_in[14];
    float* out = (float*)d_out;

    float *x_ptr, *y_ptr;
    cudaGetSymbolAddress((void**)&x_ptr, g_x);
    cudaGetSymbolAddress((void**)&y_ptr, g_y);

    const size_t SMEM_GATE = (size_t)(128 * 128 + 2 * 32 * 128) * 4;  // 98304
    const size_t SMEM_GEMM = (size_t)(128 * 128 + 64 * 128) * 4;      // 98304
    cudaFuncSetAttribute(gate_kernel, cudaFuncAttributeMaxDynamicSharedMemorySize, (int)SMEM_GATE);
    cudaFuncSetAttribute(gemm_kernel, cudaFuncAttributeMaxDynamicSharedMemorySize, (int)SMEM_GEMM);

    // Static base regions of the output
    cudaMemcpyAsync(out, user_base, (size_t)USER_NUM * H * sizeof(float),
                    cudaMemcpyDeviceToDevice, 0);
    cudaMemcpyAsync(out + (size_t)(USER_NUM + T_SLICES * M_SUB) * H, item_base,
                    (size_t)ITEM_NUM * H * sizeof(float), cudaMemcpyDeviceToDevice, 0);

    const size_t USER_TOT = USER_NUM + (size_t)T_SLICES * M_SUB;   // 50000

    for (int t = 0; t < T_SLICES; t++) {
        // 1) gated fusion -> g_x
        gate_kernel<<<N_SUB / 32, 256, SMEM_GATE>>>(
            item_base, item_dy,
            W_gate + (size_t)t * H * H, b_gate + (size_t)t * H,
            rev_i + (size_t)t * N_SUB, rev_li + (size_t)t * N_SUB, x_ptr);

        // 2) two HGNN layers: y = (relu?)x @ W + b ; x = G-spmm(y)  (relu deferred to consumer)
        for (int l = 0; l < 2; l++) {
            gemm_kernel<<<(N_SUB + 63) / 64, 256, SMEM_GEMM>>>(
                x_ptr,
                W_hgnn + (size_t)(t * 2 + l) * H * H,
                b_hgnn + (size_t)(t * 2 + l) * H,
                y_ptr, (l == 1) ? 1 : 0, N_SUB);
            cudaMemsetAsync(x_ptr, 0, (size_t)N_SUB * H * sizeof(float), 0);
            spmm_kernel<<<1184, 256>>>(g_rows + (size_t)t * NNZ_G,
                                       g_cols + (size_t)t * NNZ_G,
                                       g_vals + (size_t)t * NNZ_G,
                                       NNZ_G, y_ptr, x_ptr);
        }

        // 3) item output: relu(x) -> item_buf slice t  (also the SpMM-E input)
        float* out_x = out + (USER_TOT + (size_t)ITEM_NUM + (size_t)t * N_SUB) * H;
        relu_copy_kernel<<<(N_SUB * H / 4 + 255) / 256, 256>>>(x_ptr, out_x, N_SUB * H / 4);

        // 4) edges: user_buf slice t = E-spmm(relu(x))
        float* out_e = out + ((size_t)USER_NUM + (size_t)t * M_SUB) * H;
        cudaMemsetAsync(out_e, 0, (size_t)M_SUB * H * sizeof(float), 0);
        spmm_kernel<<<1184, 256>>>(e_rows + (size_t)t * NNZ_E,
                                   e_cols + (size_t)t * NNZ_E,
                                   e_vals + (size_t)t * NNZ_E,
                                   NNZ_E, out_x, out_e);
    }
}

// round 9
// speedup vs baseline: 1.2585x; 1.2585x over previous
#include <cuda_runtime.h>
#include <cuda_bf16.h>
#include <cstdint>

// Problem constants (match reference)
#define T_SLICES 8
#define N_SUB    20000
#define M_SUB    5000
#define H        128
#define NNZ_G    200000
#define NNZ_E    100000
#define ITEM_NUM 40000
#define USER_NUM 10000

// Smem GEMM staging: 4 matrices of 128 rows x 136 bf16 (136 = 128 + 8 pad for
// conflict-free ldmatrix: row stride 272B -> +4 banks/row).
#define LDP       136
#define MAT_BYTES (128 * LDP * 2)          // 34816
#define SMEM_REQ  (4 * MAT_BYTES)          // 139264

// Scratch (no allocations allowed -> __device__ globals)
__device__ float g_x[(size_t)T_SLICES * N_SUB * H];   // 80 MB
__device__ float g_y[(size_t)T_SLICES * N_SUB * H];   // 80 MB
__device__ __nv_bfloat16 g_WTh[24 * H * H];           // transposed W, bf16 hi
__device__ __nv_bfloat16 g_WTl[24 * H * H];           // transposed W, bf16 lo

// ---------------------------------------------------------------------------
// helpers
// ---------------------------------------------------------------------------
__device__ __forceinline__ uint32_t smem_u32(const void* p) {
    return (uint32_t)__cvta_generic_to_shared(p);
}

__device__ __forceinline__ void ldm_x4(uint32_t addr, uint32_t* r) {
    asm volatile("ldmatrix.sync.aligned.m8n8.x4.shared.b16 {%0,%1,%2,%3}, [%4];"
                 : "=r"(r[0]), "=r"(r[1]), "=r"(r[2]), "=r"(r[3]) : "r"(addr));
}

__device__ __forceinline__ void mma16816(float* d, const uint32_t* a, const uint32_t* b) {
    asm volatile(
        "mma.sync.aligned.m16n8k16.row.col.f32.bf16.bf16.f32 "
        "{%0,%1,%2,%3}, {%4,%5,%6,%7}, {%8,%9}, {%0,%1,%2,%3};"
        : "+f"(d[0]), "+f"(d[1]), "+f"(d[2]), "+f"(d[3])
        : "r"(a[0]), "r"(a[1]), "r"(a[2]), "r"(a[3]), "r"(b[0]), "r"(b[1]));
}

// bf16 hi/lo split of a float4, packed as two bf16x2 words each
__device__ __forceinline__ void split4(float4 v, uint2& hi, uint2& lo) {
    __nv_bfloat162 h01 = __floats2bfloat162_rn(v.x, v.y);
    __nv_bfloat162 h23 = __floats2bfloat162_rn(v.z, v.w);
    __nv_bfloat162 l01 = __floats2bfloat162_rn(v.x - __bfloat162float(h01.x),
                                               v.y - __bfloat162float(h01.y));
    __nv_bfloat162 l23 = __floats2bfloat162_rn(v.z - __bfloat162float(h23.x),
                                               v.w - __bfloat162float(h23.y));
    hi.x = *(uint32_t*)&h01; hi.y = *(uint32_t*)&h23;
    lo.x = *(uint32_t*)&l01; lo.y = *(uint32_t*)&l23;
}

// ---------------------------------------------------------------------------
// HMMA mainloop: D[128x128] += [Ah|Al|Ah](128x384) @ [Wh|Wh|Wl]^T
// Warp w: rows (w>>1)*32, cols (w&1)*64. A smem [m][k] (LDP), W smem [n][k].
// Both operands use PLAIN ldmatrix (col-major B frag == row-major frag of W^T).
// ---------------------------------------------------------------------------
__device__ __forceinline__ void gemm_mainloop(uint32_t sAh, uint32_t sAl,
                                              uint32_t sWh, uint32_t sWl,
                                              int w, int lane, float (&D)[2][8][4])
{
    const int m_base = (w >> 1) * 32;
    const int n_base = (w & 1) * 64;
    uint32_t aoff[2], boff[4];
#pragma unroll
    for (int i = 0; i < 2; i++)
        aoff[i] = (uint32_t)(((m_base + i * 16 + (lane & 15)) * LDP +
                              ((lane >> 4) << 3)) * 2);
#pragma unroll
    for (int jt = 0; jt < 4; jt++)
        boff[jt] = (uint32_t)(((n_base + jt * 16 + ((lane >> 4) << 3) + (lane & 7)) * LDP +
                               (((lane >> 3) & 1) << 3)) * 2);

    const uint32_t aBase[3] = {sAh, sAl, sAh};
    const uint32_t wBase[3] = {sWh, sWh, sWl};
#pragma unroll
    for (int p = 0; p < 3; p++) {
#pragma unroll
        for (int k = 0; k < 8; k++) {
            uint32_t af[2][4], bf[4][4];
            ldm_x4(aBase[p] + aoff[0] + k * 32, af[0]);
            ldm_x4(aBase[p] + aoff[1] + k * 32, af[1]);
#pragma unroll
            for (int jt = 0; jt < 4; jt++)
                ldm_x4(wBase[p] + boff[jt] + k * 32, bf[jt]);
#pragma unroll
            for (int i = 0; i < 2; i++)
#pragma unroll
                for (int j = 0; j < 8; j++)
                    mma16816(D[i][j], af[i], bf[j >> 1] + (j & 1) * 2);
        }
    }
}

// Load W tiles (transposed+split, [n][k] row-major, contiguous 128) into padded smem
__device__ __forceinline__ void load_w_smem(__nv_bfloat16* pWh, __nv_bfloat16* pWl,
                                            int wi, int r, int half)
{
    const float4* sh = (const float4*)(g_WTh + (size_t)wi * H * H);
    const float4* sl = (const float4*)(g_WTl + (size_t)wi * H * H);
#pragma unroll
    for (int j = 0; j < 8; j++) {
        int si = r * 16 + half * 8 + j;          // row r = 16 float4
        int e  = r * LDP + half * 64 + j * 8;
        *(float4*)(pWh + e) = sh[si];
        *(float4*)(pWl + e) = sl[si];
    }
}

// ---------------------------------------------------------------------------
// Prep: W[k][n] fp32 -> WT[n][k] bf16 hi/lo (24 matrices: 8 gate + 16 hgnn)
// ---------------------------------------------------------------------------
__global__ void prep_w(const float* __restrict__ W_gate, const float* __restrict__ W_hgnn)
{
    const int m = blockIdx.x;
    const float* src = (m < 8) ? (W_gate + (size_t)m * H * H)
                               : (W_hgnn + (size_t)(m - 8) * H * H);
    __nv_bfloat16* oh = g_WTh + (size_t)m * H * H;
    __nv_bfloat16* ol = g_WTl + (size_t)m * H * H;
    for (int idx = threadIdx.x; idx < H * H; idx += blockDim.x) {
        int k = idx >> 7, n = idx & 127;
        float v = src[k * H + n];
        __nv_bfloat16 h = __float2bfloat16(v);
        __nv_bfloat16 l = __float2bfloat16(v - __bfloat162float(h));
        oh[n * H + k] = h;
        ol[n * H + k] = l;
    }
}

// ---------------------------------------------------------------------------
// HGNN GEMM: out[n,:] = (relu?)in[n,:] @ W + b    grid(157, T), 256 thr
// ---------------------------------------------------------------------------
__global__ void __launch_bounds__(256)
gemm_hmma(const float* __restrict__ xin, const float* __restrict__ bias_base,
          float* __restrict__ yout, int l, int relu_in)
{
    extern __shared__ char smem[];
    __nv_bfloat16* pAh = (__nv_bfloat16*)smem;
    __nv_bfloat16* pAl = pAh + 128 * LDP;
    __nv_bfloat16* pWh = pAl + 128 * LDP;
    __nv_bfloat16* pWl = pWh + 128 * LDP;

    const int tid = threadIdx.x, w = tid >> 5, lane = tid & 31;
    const int t = blockIdx.y;
    const int wi = 8 + t * 2 + l;
    const float* in  = xin  + (size_t)t * N_SUB * H;
    float*       out = yout + (size_t)t * N_SUB * H;
    const float* bias = bias_base + (size_t)(t * 2 + l) * H;

    {   // stage A (fp32 -> bf16 hi/lo) and W
        const int r = tid >> 1, half = tid & 1;
        int n = blockIdx.x * 128 + r; if (n >= N_SUB) n = N_SUB - 1;
        const float4* src = (const float4*)(in + (size_t)n * H + half * 64);
#pragma unroll
        for (int j = 0; j < 16; j++) {
            float4 v = src[j];
            if (relu_in) {
                v.x = fmaxf(v.x, 0.f); v.y = fmaxf(v.y, 0.f);
                v.z = fmaxf(v.z, 0.f); v.w = fmaxf(v.w, 0.f);
            }
            uint2 hi, lo; split4(v, hi, lo);
            int e = r * LDP + half * 64 + j * 4;
            *(uint2*)(pAh + e) = hi;
            *(uint2*)(pAl + e) = lo;
        }
        load_w_smem(pWh, pWl, wi, r, half);
    }
    __syncthreads();

    float D[2][8][4];
#pragma unroll
    for (int i = 0; i < 2; i++)
#pragma unroll
        for (int j = 0; j < 8; j++)
#pragma unroll
            for (int q = 0; q < 4; q++) D[i][j][q] = 0.f;

    gemm_mainloop(smem_u32(pAh), smem_u32(pAl), smem_u32(pWh), smem_u32(pWl),
                  w, lane, D);

    const int groupid = lane >> 2, tid4 = lane & 3;
    const int m_base = (w >> 1) * 32, n_base = (w & 1) * 64;
#pragma unroll
    for (int i = 0; i < 2; i++) {
#pragma unroll
        for (int k2 = 0; k2 < 2; k2++) {
            const int row = m_base + i * 16 + groupid + k2 * 8;
            const int n = blockIdx.x * 128 + row;
            if (n < N_SUB) {
                float* orow = out + (size_t)n * H;
#pragma unroll
                for (int j = 0; j < 8; j++) {
                    const int col = n_base + j * 8 + tid4 * 2;
                    const float2 bv = *(const float2*)(bias + col);
                    float2 o = { D[i][j][k2 * 2]     + bv.x,
                                 D[i][j][k2 * 2 + 1] + bv.y };
                    *(float2*)(orow + col) = o;
                }
            }
        }
    }
}

// ---------------------------------------------------------------------------
// Gate: 64 nodes/CTA. A rows 0-63 = item_base gather, 64-127 = item_dy gather.
// D = A @ Wg^T; x[node] = sig(D0+b)*a0 + sig(D1+b)*a1.  grid(313, T)
// a1 half staged through smem P (reuses pWh after mainloop).
// ---------------------------------------------------------------------------
__global__ void __launch_bounds__(256)
gate_hmma(const float* __restrict__ item_base, const float* __restrict__ item_dy,
          const float* __restrict__ b_gate,
          const int* __restrict__ rev_all, const int* __restrict__ revdy_all,
          float* __restrict__ xout)
{
    extern __shared__ char smem[];
    __nv_bfloat16* pAh = (__nv_bfloat16*)smem;
    __nv_bfloat16* pAl = pAh + 128 * LDP;
    __nv_bfloat16* pWh = pAl + 128 * LDP;
    __nv_bfloat16* pWl = pWh + 128 * LDP;
    float* P = (float*)pWh;                     // 64 x LDP fp32 = 34816 B (fits)

    const int tid = threadIdx.x, w = tid >> 5, lane = tid & 31;
    const int t = blockIdx.y;
    const int* rev   = rev_all   + (size_t)t * N_SUB;
    const int* revdy = revdy_all + (size_t)t * N_SUB;
    const float* bias = b_gate + (size_t)t * H;
    float* out = xout + (size_t)t * N_SUB * H;

    {   // gather + split A, load W
        const int r = tid >> 1, half = tid & 1;
        const int il = r & 63;
        int node = blockIdx.x * 64 + il; if (node >= N_SUB) node = N_SUB - 1;
        const float* srow = (r < 64) ? item_base + (size_t)rev[node]   * H
                                     : item_dy   + (size_t)revdy[node] * H;
        const float4* src = (const float4*)(srow + half * 64);
#pragma unroll
        for (int j = 0; j < 16; j++) {
            uint2 hi, lo; split4(src[j], hi, lo);
            int e = r * LDP + half * 64 + j * 4;
            *(uint2*)(pAh + e) = hi;
            *(uint2*)(pAl + e) = lo;
        }
        load_w_smem(pWh, pWl, t, r, half);
    }
    __syncthreads();

    float D[2][8][4];
#pragma unroll
    for (int i = 0; i < 2; i++)
#pragma unroll
        for (int j = 0; j < 8; j++)
#pragma unroll
            for (int q = 0; q < 4; q++) D[i][j][q] = 0.f;

    gemm_mainloop(smem_u32(pAh), smem_u32(pAl), smem_u32(pWh), smem_u32(pWl),
                  w, lane, D);

    // Transform D in place: v = (Ah+Al) * sigmoid(D + bias)
    const int groupid = lane >> 2, tid4 = lane & 3;
    const int m_base = (w >> 1) * 32, n_base = (w & 1) * 64;
#pragma unroll
    for (int i = 0; i < 2; i++) {
#pragma unroll
        for (int k2 = 0; k2 < 2; k2++) {
            const int row = m_base + i * 16 + groupid + k2 * 8;
#pragma unroll
            for (int j = 0; j < 8; j++) {
                const int col = n_base + j * 8 + tid4 * 2;
                const float2 bv = *(const float2*)(bias + col);
                const int e = row * LDP + col;
                uint32_t hw = *(const uint32_t*)(pAh + e);
                uint32_t lw = *(const uint32_t*)(pAl + e);
                __nv_bfloat162 h2 = *(__nv_bfloat162*)&hw;
                __nv_bfloat162 l2 = *(__nv_bfloat162*)&lw;
                float a0f = __bfloat162float(h2.x) + __bfloat162float(l2.x);
                float a1f = __bfloat162float(h2.y) + __bfloat162float(l2.y);
                float z0 = D[i][j][k2 * 2]     + bv.x;
                float z1 = D[i][j][k2 * 2 + 1] + bv.y;
                D[i][j][k2 * 2]     = a0f / (1.f + __expf(-z0));
                D[i][j][k2 * 2 + 1] = a1f / (1.f + __expf(-z1));
            }
        }
    }
    __syncthreads();                 // all warps past mainloop; pWh reusable as P

    if (w >= 4) {                    // rows 64..127 -> stage into P[row-64][col]
#pragma unroll
        for (int i = 0; i < 2; i++)
#pragma unroll
            for (int k2 = 0; k2 < 2; k2++) {
                const int row = m_base + i * 16 + groupid + k2 * 8;
                const int il = row - 64;
#pragma unroll
                for (int j = 0; j < 8; j++) {
                    const int col = n_base + j * 8 + tid4 * 2;
                    float2 v = { D[i][j][k2 * 2], D[i][j][k2 * 2 + 1] };
                    *(float2*)(P + il * LDP + col) = v;
                }
            }
    }
    __syncthreads();

    if (w < 4) {                     // rows 0..63 -> combine and store
#pragma unroll
        for (int i = 0; i < 2; i++)
#pragma unroll
            for (int k2 = 0; k2 < 2; k2++) {
                const int row = m_base + i * 16 + groupid + k2 * 8;
                const int node = blockIdx.x * 64 + row;
                if (node < N_SUB) {
                    float* orow = out + (size_t)node * H;
#pragma unroll
                    for (int j = 0; j < 8; j++) {
                        const int col = n_base + j * 8 + tid4 * 2;
                        const float2 pv = *(const float2*)(P + row * LDP + col);
                        float2 o = { D[i][j][k2 * 2]     + pv.x,
                                     D[i][j][k2 * 2 + 1] + pv.y };
                        *(float2*)(orow + col) = o;
                    }
                }
            }
    }
}

// ---------------------------------------------------------------------------
// SpMM (COO): out[rows[e], :] += vals[e] * in[cols[e], :]   (warp per nnz)
// ---------------------------------------------------------------------------
__global__ void spmm_kernel(const int* __restrict__ rows, const int* __restrict__ cols,
                            const float* __restrict__ vals, int nnz,
                            const float* __restrict__ in, float* __restrict__ out)
{
    const int lane   = threadIdx.x & 31;
    const int warp   = (blockIdx.x * blockDim.x + threadIdx.x) >> 5;
    const int nwarps = (gridDim.x * blockDim.x) >> 5;

    for (int e = warp; e < nnz; e += nwarps) {
        const int   rr = rows[e];
        const int   c  = cols[e];
        const float v  = vals[e];
        const float4 x = *(const float4*)(in + (size_t)c * H + lane * 4);
        float* p = out + (size_t)rr * H + lane * 4;
        asm volatile("red.global.add.v4.f32 [%0], {%1,%2,%3,%4};"
                     :: "l"(p), "f"(x.x * v), "f"(x.y * v), "f"(x.z * v), "f"(x.w * v)
                     : "memory");
    }
}

__global__ void relu_copy_kernel(const float* __restrict__ in, float* __restrict__ out, int n4)
{
    int i = blockIdx.x * blockDim.x + threadIdx.x;
    if (i < n4) {
        float4 v = ((const float4*)in)[i];
        v.x = fmaxf(v.x, 0.f); v.y = fmaxf(v.y, 0.f);
        v.z = fmaxf(v.z, 0.f); v.w = fmaxf(v.w, 0.f);
        ((float4*)out)[i] = v;
    }
}

extern "C" void kernel_launch(void* const* d_in, const int* in_sizes, int n_in,
                              void* d_out, int out_size)
{
    const float* item_base = (const float*)d_in[0];
    const float* user_base = (const float*)d_in[1];
    const float* item_dy   = (const float*)d_in[2];
    const float* W_gate    = (const float*)d_in[3];
    const float* b_gate    = (const float*)d_in[4];
    const float* W_hgnn    = (const float*)d_in[5];
    const float* b_hgnn    = (const float*)d_in[6];
    const float* g_vals    = (const float*)d_in[7];
    const float* e_vals    = (const float*)d_in[8];
    const int*   rev_i     = (const int*)d_in[9];
    const int*   rev_li    = (const int*)d_in[10];
    const int*   g_rows    = (const int*)d_in[11];
    const int*   g_cols    = (const int*)d_in[12];
    const int*   e_rows    = (const int*)d_in[13];
    const int*   e_cols    = (const int*)d_in[14];
    float* out = (float*)d_out;

    float *x_ptr, *y_ptr;
    cudaGetSymbolAddress((void**)&x_ptr, g_x);
    cudaGetSymbolAddress((void**)&y_ptr, g_y);

    cudaFuncSetAttribute(gemm_hmma, cudaFuncAttributeMaxDynamicSharedMemorySize, SMEM_REQ);
    cudaFuncSetAttribute(gate_hmma, cudaFuncAttributeMaxDynamicSharedMemorySize, SMEM_REQ);

    // Weight transpose + bf16 split (tiny: 24 x 128 x 128)
    prep_w<<<24, 256>>>(W_gate, W_hgnn);

    // Static base regions of the output
    cudaMemcpyAsync(out, user_base, (size_t)USER_NUM * H * sizeof(float),
                    cudaMemcpyDeviceToDevice, 0);
    cudaMemcpyAsync(out + (size_t)(USER_NUM + T_SLICES * M_SUB) * H, item_base,
                    (size_t)ITEM_NUM * H * sizeof(float), cudaMemcpyDeviceToDevice, 0);
    // Zero all hyperedge output rows at once (contiguous)
    cudaMemsetAsync(out + (size_t)USER_NUM * H, 0,
                    (size_t)T_SLICES * M_SUB * H * sizeof(float), 0);

    const size_t USER_TOT = USER_NUM + (size_t)T_SLICES * M_SUB;   // 50000

    // 1) gated fusion, all slices batched -> g_x
    gate_hmma<<<dim3((N_SUB + 63) / 64, T_SLICES), 256, SMEM_REQ>>>(
        item_base, item_dy, b_gate, rev_i, rev_li, x_ptr);

    // 2) two HGNN layers (GEMM batched across slices; SpMM per slice for L2 locality)
    for (int l = 0; l < 2; l++) {
        gemm_hmma<<<dim3((N_SUB + 127) / 128, T_SLICES), 256, SMEM_REQ>>>(
            x_ptr, b_hgnn, y_ptr, l, (l == 1) ? 1 : 0);
        cudaMemsetAsync(x_ptr, 0, (size_t)T_SLICES * N_SUB * H * sizeof(float), 0);
        for (int t = 0; t < T_SLICES; t++) {
            spmm_kernel<<<1184, 256>>>(g_rows + (size_t)t * NNZ_G,
                                       g_cols + (size_t)t * NNZ_G,
                                       g_vals + (size_t)t * NNZ_G, NNZ_G,
                                       y_ptr + (size_t)t * N_SUB * H,
                                       x_ptr + (size_t)t * N_SUB * H);
        }
    }

    // 3) item outputs: relu(x) -> item_buf slices (contiguous, all slices at once)
    float* out_items = out + (USER_TOT + (size_t)ITEM_NUM) * H;
    {
        int n4 = T_SLICES * N_SUB * H / 4;
        relu_copy_kernel<<<(n4 + 255) / 256, 256>>>(x_ptr, out_items, n4);
    }

    // 4) edges: user_buf slice t = E-spmm(relu(x_t))
    for (int t = 0; t < T_SLICES; t++) {
        spmm_kernel<<<1184, 256>>>(e_rows + (size_t)t * NNZ_E,
                                   e_cols + (size_t)t * NNZ_E,
                                   e_vals + (size_t)t * NNZ_E, NNZ_E,
                                   out_items + (size_t)t * N_SUB * H,
                                   out + ((size_t)USER_NUM + (size_t)t * M_SUB) * H);
    }
}

// round 11
// speedup vs baseline: 1.5686x; 1.2464x over previous
#include <cuda_runtime.h>
#include <cuda_bf16.h>
#include <cstdint>

// Problem constants (match reference)
#define T_SLICES 8
#define N_SUB    20000
#define M_SUB    5000
#define H        128
#define NNZ_G    200000
#define NNZ_E    100000
#define ITEM_NUM 40000
#define USER_NUM 10000

// Smem GEMM staging: 4 matrices of 128 rows x 136 bf16 (136 = 128 + 8 pad for
// conflict-free ldmatrix: row stride 272B -> +4 banks/row).
#define LDP       136
#define MAT_BYTES (128 * LDP * 2)          // 34816
#define SMEM_REQ  (4 * MAT_BYTES)          // 139264

// Scratch (no allocations allowed -> __device__ globals)
__device__ float g_x[(size_t)T_SLICES * N_SUB * H];   // 80 MB
__device__ float g_y[(size_t)T_SLICES * N_SUB * H];   // 80 MB
__device__ __nv_bfloat16 g_WTh[24 * H * H];           // transposed W, bf16 hi
__device__ __nv_bfloat16 g_WTl[24 * H * H];           // transposed W, bf16 lo

// CSR scratch (built per call from COO inputs)
__device__ int   g_cntG[T_SLICES * N_SUB];
__device__ int   g_rpG [T_SLICES * (N_SUB + 1)];
__device__ int   g_curG[T_SLICES * N_SUB];
__device__ int   g_colG[(size_t)T_SLICES * NNZ_G];
__device__ float g_valG[(size_t)T_SLICES * NNZ_G];
__device__ int   g_cntE[T_SLICES * M_SUB];
__device__ int   g_rpE [T_SLICES * (M_SUB + 1)];
__device__ int   g_curE[T_SLICES * M_SUB];
__device__ int   g_colE[(size_t)T_SLICES * NNZ_E];
__device__ float g_valE[(size_t)T_SLICES * NNZ_E];

// ---------------------------------------------------------------------------
// helpers
// ---------------------------------------------------------------------------
__device__ __forceinline__ uint32_t smem_u32(const void* p) {
    return (uint32_t)__cvta_generic_to_shared(p);
}

__device__ __forceinline__ void ldm_x4(uint32_t addr, uint32_t* r) {
    asm volatile("ldmatrix.sync.aligned.m8n8.x4.shared.b16 {%0,%1,%2,%3}, [%4];"
                 : "=r"(r[0]), "=r"(r[1]), "=r"(r[2]), "=r"(r[3]) : "r"(addr));
}

__device__ __forceinline__ void mma16816(float* d, const uint32_t* a, const uint32_t* b) {
    asm volatile(
        "mma.sync.aligned.m16n8k16.row.col.f32.bf16.bf16.f32 "
        "{%0,%1,%2,%3}, {%4,%5,%6,%7}, {%8,%9}, {%0,%1,%2,%3};"
        : "+f"(d[0]), "+f"(d[1]), "+f"(d[2]), "+f"(d[3])
        : "r"(a[0]), "r"(a[1]), "r"(a[2]), "r"(a[3]), "r"(b[0]), "r"(b[1]));
}

__device__ __forceinline__ void split4(float4 v, uint2& hi, uint2& lo) {
    __nv_bfloat162 h01 = __floats2bfloat162_rn(v.x, v.y);
    __nv_bfloat162 h23 = __floats2bfloat162_rn(v.z, v.w);
    __nv_bfloat162 l01 = __floats2bfloat162_rn(v.x - __bfloat162float(h01.x),
                                               v.y - __bfloat162float(h01.y));
    __nv_bfloat162 l23 = __floats2bfloat162_rn(v.z - __bfloat162float(h23.x),
                                               v.w - __bfloat162float(h23.y));
    hi.x = *(uint32_t*)&h01; hi.y = *(uint32_t*)&h23;
    lo.x = *(uint32_t*)&l01; lo.y = *(uint32_t*)&l23;
}

// ---------------------------------------------------------------------------
// HMMA mainloop: D[128x128] += [Ah|Al|Ah](128x384) @ [Wh|Wh|Wl]^T
// ---------------------------------------------------------------------------
__device__ __forceinline__ void gemm_mainloop(uint32_t sAh, uint32_t sAl,
                                              uint32_t sWh, uint32_t sWl,
                                              int w, int lane, float (&D)[2][8][4])
{
    const int m_base = (w >> 1) * 32;
    const int n_base = (w & 1) * 64;
    uint32_t aoff[2], boff[4];
#pragma unroll
    for (int i = 0; i < 2; i++)
        aoff[i] = (uint32_t)(((m_base + i * 16 + (lane & 15)) * LDP +
                              ((lane >> 4) << 3)) * 2);
#pragma unroll
    for (int jt = 0; jt < 4; jt++)
        boff[jt] = (uint32_t)(((n_base + jt * 16 + ((lane >> 4) << 3) + (lane & 7)) * LDP +
                               (((lane >> 3) & 1) << 3)) * 2);

    const uint32_t aBase[3] = {sAh, sAl, sAh};
    const uint32_t wBase[3] = {sWh, sWh, sWl};
#pragma unroll
    for (int p = 0; p < 3; p++) {
#pragma unroll
        for (int k = 0; k < 8; k++) {
            uint32_t af[2][4], bf[4][4];
            ldm_x4(aBase[p] + aoff[0] + k * 32, af[0]);
            ldm_x4(aBase[p] + aoff[1] + k * 32, af[1]);
#pragma unroll
            for (int jt = 0; jt < 4; jt++)
                ldm_x4(wBase[p] + boff[jt] + k * 32, bf[jt]);
#pragma unroll
            for (int i = 0; i < 2; i++)
#pragma unroll
                for (int j = 0; j < 8; j++)
                    mma16816(D[i][j], af[i], bf[j >> 1] + (j & 1) * 2);
        }
    }
}

__device__ __forceinline__ void load_w_smem(__nv_bfloat16* pWh, __nv_bfloat16* pWl,
                                            int wi, int r, int half)
{
    const float4* sh = (const float4*)(g_WTh + (size_t)wi * H * H);
    const float4* sl = (const float4*)(g_WTl + (size_t)wi * H * H);
#pragma unroll
    for (int j = 0; j < 8; j++) {
        int si = r * 16 + half * 8 + j;
        int e  = r * LDP + half * 64 + j * 8;
        *(float4*)(pWh + e) = sh[si];
        *(float4*)(pWl + e) = sl[si];
    }
}

// ---------------------------------------------------------------------------
// Prep: W[k][n] fp32 -> WT[n][k] bf16 hi/lo (24 matrices: 8 gate + 16 hgnn)
// ---------------------------------------------------------------------------
__global__ void prep_w(const float* __restrict__ W_gate, const float* __restrict__ W_hgnn)
{
    const int m = blockIdx.x;
    const float* src = (m < 8) ? (W_gate + (size_t)m * H * H)
                               : (W_hgnn + (size_t)(m - 8) * H * H);
    __nv_bfloat16* oh = g_WTh + (size_t)m * H * H;
    __nv_bfloat16* ol = g_WTl + (size_t)m * H * H;
    for (int idx = threadIdx.x; idx < H * H; idx += blockDim.x) {
        int k = idx >> 7, n = idx & 127;
        float v = src[k * H + n];
        __nv_bfloat16 h = __float2bfloat16(v);
        __nv_bfloat16 l = __float2bfloat16(v - __bfloat162float(h));
        oh[n * H + k] = h;
        ol[n * H + k] = l;
    }
}

// ---------------------------------------------------------------------------
// CSR build: histogram -> per-slice block scan -> scatter (col,val) pairs
// ---------------------------------------------------------------------------
__global__ void hist_kernel(const int* __restrict__ rows_all, int nnz,
                            int* __restrict__ cnt_all, int nrows)
{
    const int t = blockIdx.y;
    const int e = blockIdx.x * blockDim.x + threadIdx.x;
    if (e < nnz)
        atomicAdd(&cnt_all[(size_t)t * nrows + rows_all[(size_t)t * nnz + e]], 1);
}

__global__ void scan_kernel(const int* __restrict__ cnt_all, int* __restrict__ rowptr_all,
                            int* __restrict__ cursor_all, int nrows)
{
    const int t = blockIdx.x;
    const int* cnt = cnt_all + (size_t)t * nrows;
    int* rowptr = rowptr_all + (size_t)t * (nrows + 1);
    int* cursor = cursor_all + (size_t)t * nrows;
    __shared__ int part[256];
    const int tid = threadIdx.x;
    const int chunk = (nrows + 255) / 256;
    const int lo = tid * chunk;
    const int hi = min(lo + chunk, nrows);
    int s = 0;
    for (int r = lo; r < hi; r++) s += cnt[r];
    part[tid] = s;
    __syncthreads();
    // Hillis-Steele inclusive scan over 256 partials
    for (int off = 1; off < 256; off <<= 1) {
        int v = (tid >= off) ? part[tid - off] : 0;
        __syncthreads();
        part[tid] += v;
        __syncthreads();
    }
    int prefix = (tid == 0) ? 0 : part[tid - 1];
    for (int r = lo; r < hi; r++) {
        rowptr[r] = prefix;
        cursor[r] = prefix;
        prefix += cnt[r];
    }
    if (tid == 255) rowptr[nrows] = part[255];
}

__global__ void scatter_kernel(const int* __restrict__ rows_all,
                               const int* __restrict__ cols_all,
                               const float* __restrict__ vals_all, int nnz,
                               int* __restrict__ cursor_all, int nrows,
                               int* __restrict__ ccol_all, float* __restrict__ cval_all)
{
    const int t = blockIdx.y;
    const int e = blockIdx.x * blockDim.x + threadIdx.x;
    if (e < nnz) {
        const size_t base = (size_t)t * nnz;
        const int r = rows_all[base + e];
        const int pos = atomicAdd(&cursor_all[(size_t)t * nrows + r], 1);
        ccol_all[(size_t)t * nnz + pos] = cols_all[base + e];
        cval_all[(size_t)t * nnz + pos] = vals_all[base + e];
    }
}

// ---------------------------------------------------------------------------
// CSR SpMM: warp per row, full row sum in registers, single store, fused relu.
// ---------------------------------------------------------------------------
__global__ void __launch_bounds__(256)
spmm_csr(const int* __restrict__ rowptr_all, const int* __restrict__ ccol_all,
         const float* __restrict__ cval_all, int nrows, int nnz,
         const float* __restrict__ in_all, size_t in_stride,
         float* __restrict__ out_all, size_t out_stride, int relu_out)
{
    const int t = blockIdx.y;
    const int row = (blockIdx.x * blockDim.x + threadIdx.x) >> 5;
    if (row >= nrows) return;
    const int lane = threadIdx.x & 31;

    const int* rowptr = rowptr_all + (size_t)t * (nrows + 1);
    const int* ccol = ccol_all + (size_t)t * nnz;
    const float* cval = cval_all + (size_t)t * nnz;
    const float* in = in_all + (size_t)t * in_stride;
    float* out = out_all + (size_t)t * out_stride;

    const int s = rowptr[row], e = rowptr[row + 1];
    float4 acc = make_float4(0.f, 0.f, 0.f, 0.f);
    int j = s;
    for (; j + 1 < e; j += 2) {
        const int   c0 = ccol[j],     c1 = ccol[j + 1];
        const float v0 = cval[j],     v1 = cval[j + 1];
        const float4 x0 = *(const float4*)(in + (size_t)c0 * H + lane * 4);
        const float4 x1 = *(const float4*)(in + (size_t)c1 * H + lane * 4);
        acc.x += v0 * x0.x + v1 * x1.x;
        acc.y += v0 * x0.y + v1 * x1.y;
        acc.z += v0 * x0.z + v1 * x1.z;
        acc.w += v0 * x0.w + v1 * x1.w;
    }
    if (j < e) {
        const float v0 = cval[j];
        const float4 x0 = *(const float4*)(in + (size_t)ccol[j] * H + lane * 4);
        acc.x += v0 * x0.x; acc.y += v0 * x0.y;
        acc.z += v0 * x0.z; acc.w += v0 * x0.w;
    }
    if (relu_out) {
        acc.x = fmaxf(acc.x, 0.f); acc.y = fmaxf(acc.y, 0.f);
        acc.z = fmaxf(acc.z, 0.f); acc.w = fmaxf(acc.w, 0.f);
    }
    *(float4*)(out + (size_t)row * H + lane * 4) = acc;
}

// ---------------------------------------------------------------------------
// HGNN GEMM: out[n,:] = in[n,:] @ W + b    grid(157, T), 256 thr
// ---------------------------------------------------------------------------
__global__ void __launch_bounds__(256)
gemm_hmma(const float* __restrict__ xin, const float* __restrict__ bias_base,
          float* __restrict__ yout, int l)
{
    extern __shared__ char smem[];
    __nv_bfloat16* pAh = (__nv_bfloat16*)smem;
    __nv_bfloat16* pAl = pAh + 128 * LDP;
    __nv_bfloat16* pWh = pAl + 128 * LDP;
    __nv_bfloat16* pWl = pWh + 128 * LDP;

    const int tid = threadIdx.x, w = tid >> 5, lane = tid & 31;
    const int t = blockIdx.y;
    const int wi = 8 + t * 2 + l;
    const float* in  = xin  + (size_t)t * N_SUB * H;
    float*       out = yout + (size_t)t * N_SUB * H;
    const float* bias = bias_base + (size_t)(t * 2 + l) * H;

    {   // stage A (fp32 -> bf16 hi/lo) and W
        const int r = tid >> 1, half = tid & 1;
        int n = blockIdx.x * 128 + r; if (n >= N_SUB) n = N_SUB - 1;
        const float4* src = (const float4*)(in + (size_t)n * H + half * 64);
#pragma unroll
        for (int j = 0; j < 16; j++) {
            uint2 hi, lo; split4(src[j], hi, lo);
            int e = r * LDP + half * 64 + j * 4;
            *(uint2*)(pAh + e) = hi;
            *(uint2*)(pAl + e) = lo;
        }
        load_w_smem(pWh, pWl, wi, r, half);
    }
    __syncthreads();

    float D[2][8][4];
#pragma unroll
    for (int i = 0; i < 2; i++)
#pragma unroll
        for (int j = 0; j < 8; j++)
#pragma unroll
            for (int q = 0; q < 4; q++) D[i][j][q] = 0.f;

    gemm_mainloop(smem_u32(pAh), smem_u32(pAl), smem_u32(pWh), smem_u32(pWl),
                  w, lane, D);

    const int groupid = lane >> 2, tid4 = lane & 3;
    const int m_base = (w >> 1) * 32, n_base = (w & 1) * 64;
#pragma unroll
    for (int i = 0; i < 2; i++) {
#pragma unroll
        for (int k2 = 0; k2 < 2; k2++) {
            const int row = m_base + i * 16 + groupid + k2 * 8;
            const int n = blockIdx.x * 128 + row;
            if (n < N_SUB) {
                float* orow = out + (size_t)n * H;
#pragma unroll
                for (int j = 0; j < 8; j++) {
                    const int col = n_base + j * 8 + tid4 * 2;
                    const float2 bv = *(const float2*)(bias + col);
                    float2 o = { D[i][j][k2 * 2]     + bv.x,
                                 D[i][j][k2 * 2 + 1] + bv.y };
                    *(float2*)(orow + col) = o;
                }
            }
        }
    }
}

// ---------------------------------------------------------------------------
// Gate: 64 nodes/CTA. A rows 0-63 = item_base gather, 64-127 = item_dy gather.
// ---------------------------------------------------------------------------
__global__ void __launch_bounds__(256)
gate_hmma(const float* __restrict__ item_base, const float* __restrict__ item_dy,
          const float* __restrict__ b_gate,
          const int* __restrict__ rev_all, const int* __restrict__ revdy_all,
          float* __restrict__ xout)
{
    extern __shared__ char smem[];
    __nv_bfloat16* pAh = (__nv_bfloat16*)smem;
    __nv_bfloat16* pAl = pAh + 128 * LDP;
    __nv_bfloat16* pWh = pAl + 128 * LDP;
    __nv_bfloat16* pWl = pWh + 128 * LDP;
    float* P = (float*)pWh;                     // 64 x LDP fp32 staging (post-MMA)

    const int tid = threadIdx.x, w = tid >> 5, lane = tid & 31;
    const int t = blockIdx.y;
    const int* rev   = rev_all   + (size_t)t * N_SUB;
    const int* revdy = revdy_all + (size_t)t * N_SUB;
    const float* bias = b_gate + (size_t)t * H;
    float* out = xout + (size_t)t * N_SUB * H;

    {   // gather + split A, load W
        const int r = tid >> 1, half = tid & 1;
        const int il = r & 63;
        int node = blockIdx.x * 64 + il; if (node >= N_SUB) node = N_SUB - 1;
        const float* srow = (r < 64) ? item_base + (size_t)rev[node]   * H
                                     : item_dy   + (size_t)revdy[node] * H;
        const float4* src = (const float4*)(srow + half * 64);
#pragma unroll
        for (int j = 0; j < 16; j++) {
            uint2 hi, lo; split4(src[j], hi, lo);
            int e = r * LDP + half * 64 + j * 4;
            *(uint2*)(pAh + e) = hi;
            *(uint2*)(pAl + e) = lo;
        }
        load_w_smem(pWh, pWl, t, r, half);
    }
    __syncthreads();

    float D[2][8][4];
#pragma unroll
    for (int i = 0; i < 2; i++)
#pragma unroll
        for (int j = 0; j < 8; j++)
#pragma unroll
            for (int q = 0; q < 4; q++) D[i][j][q] = 0.f;

    gemm_mainloop(smem_u32(pAh), smem_u32(pAl), smem_u32(pWh), smem_u32(pWl),
                  w, lane, D);

    // v = (Ah+Al) * sigmoid(D + bias)
    const int groupid = lane >> 2, tid4 = lane & 3;
    const int m_base = (w >> 1) * 32, n_base = (w & 1) * 64;
#pragma unroll
    for (int i = 0; i < 2; i++) {
#pragma unroll
        for (int k2 = 0; k2 < 2; k2++) {
            const int row = m_base + i * 16 + groupid + k2 * 8;
#pragma unroll
            for (int j = 0; j < 8; j++) {
                const int col = n_base + j * 8 + tid4 * 2;
                const float2 bv = *(const float2*)(bias + col);
                const int e = row * LDP + col;
                uint32_t hw = *(const uint32_t*)(pAh + e);
                uint32_t lw = *(const uint32_t*)(pAl + e);
                __nv_bfloat162 h2 = *(__nv_bfloat162*)&hw;
                __nv_bfloat162 l2 = *(__nv_bfloat162*)&lw;
                float a0f = __bfloat162float(h2.x) + __bfloat162float(l2.x);
                float a1f = __bfloat162float(h2.y) + __bfloat162float(l2.y);
                float z0 = D[i][j][k2 * 2]     + bv.x;
                float z1 = D[i][j][k2 * 2 + 1] + bv.y;
                D[i][j][k2 * 2]     = a0f / (1.f + __expf(-z0));
                D[i][j][k2 * 2 + 1] = a1f / (1.f + __expf(-z1));
            }
        }
    }
    __syncthreads();

    if (w >= 4) {                    // rows 64..127 -> stage into P
#pragma unroll
        for (int i = 0; i < 2; i++)
#pragma unroll
            for (int k2 = 0; k2 < 2; k2++) {
                const int row = m_base + i * 16 + groupid + k2 * 8;
                const int il = row - 64;
#pragma unroll
                for (int j = 0; j < 8; j++) {
                    const int col = n_base + j * 8 + tid4 * 2;
                    float2 v = { D[i][j][k2 * 2], D[i][j][k2 * 2 + 1] };
                    *(float2*)(P + il * LDP + col) = v;
                }
            }
    }
    __syncthreads();

    if (w < 4) {                     // rows 0..63 -> combine and store
#pragma unroll
        for (int i = 0; i < 2; i++)
#pragma unroll
            for (int k2 = 0; k2 < 2; k2++) {
                const int row = m_base + i * 16 + groupid + k2 * 8;
                const int node = blockIdx.x * 64 + row;
                if (node < N_SUB) {
                    float* orow = out + (size_t)node * H;
#pragma unroll
                    for (int j = 0; j < 8; j++) {
                        const int col = n_base + j * 8 + tid4 * 2;
                        const float2 pv = *(const float2*)(P + row * LDP + col);
                        float2 o = { D[i][j][k2 * 2]     + pv.x,
                                     D[i][j][k2 * 2 + 1] + pv.y };
                        *(float2*)(orow + col) = o;
                    }
                }
            }
    }
}

extern "C" void kernel_launch(void* const* d_in, const int* in_sizes, int n_in,
                              void* d_out, int out_size)
{
    const float* item_base = (const float*)d_in[0];
    const float* user_base = (const float*)d_in[1];
    const float* item_dy   = (const float*)d_in[2];
    const float* W_gate    = (const float*)d_in[3];
    const float* b_gate    = (const float*)d_in[4];
    const float* W_hgnn    = (const float*)d_in[5];
    const float* b_hgnn    = (const float*)d_in[6];
    const float* g_vals    = (const float*)d_in[7];
    const float* e_vals    = (const float*)d_in[8];
    const int*   rev_i     = (const int*)d_in[9];
    const int*   rev_li    = (const int*)d_in[10];
    const int*   g_rows    = (const int*)d_in[11];
    const int*   g_cols    = (const int*)d_in[12];
    const int*   e_rows    = (const int*)d_in[13];
    const int*   e_cols    = (const int*)d_in[14];
    float* out = (float*)d_out;

    float *x_ptr, *y_ptr;
    cudaGetSymbolAddress((void**)&x_ptr, g_x);
    cudaGetSymbolAddress((void**)&y_ptr, g_y);
    int *cntG, *rpG, *curG, *colG; float* valG;
    int *cntE, *rpE, *curE, *colE; float* valE;
    cudaGetSymbolAddress((void**)&cntG, g_cntG);
    cudaGetSymbolAddress((void**)&rpG,  g_rpG);
    cudaGetSymbolAddress((void**)&curG, g_curG);
    cudaGetSymbolAddress((void**)&colG, g_colG);
    cudaGetSymbolAddress((void**)&valG, g_valG);
    cudaGetSymbolAddress((void**)&cntE, g_cntE);
    cudaGetSymbolAddress((void**)&rpE,  g_rpE);
    cudaGetSymbolAddress((void**)&curE, g_curE);
    cudaGetSymbolAddress((void**)&colE, g_colE);
    cudaGetSymbolAddress((void**)&valE, g_valE);

    cudaFuncSetAttribute(gemm_hmma, cudaFuncAttributeMaxDynamicSharedMemorySize, SMEM_REQ);
    cudaFuncSetAttribute(gate_hmma, cudaFuncAttributeMaxDynamicSharedMemorySize, SMEM_REQ);

    // Weight transpose + bf16 split (tiny: 24 x 128 x 128)
    prep_w<<<24, 256>>>(W_gate, W_hgnn);

    // Static base regions of the output
    cudaMemcpyAsync(out, user_base, (size_t)USER_NUM * H * sizeof(float),
                    cudaMemcpyDeviceToDevice, 0);
    cudaMemcpyAsync(out + (size_t)(USER_NUM + T_SLICES * M_SUB) * H, item_base,
                    (size_t)ITEM_NUM * H * sizeof(float), cudaMemcpyDeviceToDevice, 0);

    // ---- CSR build (all slices) ----
    cudaMemsetAsync(cntG, 0, sizeof(int) * T_SLICES * N_SUB, 0);
    cudaMemsetAsync(cntE, 0, sizeof(int) * T_SLICES * M_SUB, 0);
    hist_kernel<<<dim3((NNZ_G + 255) / 256, T_SLICES), 256>>>(g_rows, NNZ_G, cntG, N_SUB);
    hist_kernel<<<dim3((NNZ_E + 255) / 256, T_SLICES), 256>>>(e_rows, NNZ_E, cntE, M_SUB);
    scan_kernel<<<T_SLICES, 256>>>(cntG, rpG, curG, N_SUB);
    scan_kernel<<<T_SLICES, 256>>>(cntE, rpE, curE, M_SUB);
    scatter_kernel<<<dim3((NNZ_G + 255) / 256, T_SLICES), 256>>>(
        g_rows, g_cols, g_vals, NNZ_G, curG, N_SUB, colG, valG);
    scatter_kernel<<<dim3((NNZ_E + 255) / 256, T_SLICES), 256>>>(
        e_rows, e_cols, e_vals, NNZ_E, curE, M_SUB, colE, valE);

    const size_t USER_TOT = USER_NUM + (size_t)T_SLICES * M_SUB;   // 50000
    float* out_items = out + (USER_TOT + (size_t)ITEM_NUM) * H;

    // 1) gated fusion, all slices batched -> g_x
    gate_hmma<<<dim3((N_SUB + 63) / 64, T_SLICES), 256, SMEM_REQ>>>(
        item_base, item_dy, b_gate, rev_i, rev_li, x_ptr);

    // 2) two HGNN layers. SpMM fuses the post-aggregation relu; layer 1's
    //    SpMM writes relu(x) directly into the item output region.
    for (int l = 0; l < 2; l++) {
        gemm_hmma<<<dim3((N_SUB + 127) / 128, T_SLICES), 256, SMEM_REQ>>>(
            x_ptr, b_hgnn, y_ptr, l);
        float* dst = (l == 0) ? x_ptr : out_items;
        size_t dst_stride = (size_t)N_SUB * H;
        spmm_csr<<<dim3(N_SUB / 8, T_SLICES), 256>>>(
            rpG, colG, valG, N_SUB, NNZ_G,
            y_ptr, (size_t)N_SUB * H, dst, dst_stride, 1);
    }

    // 3) edges: user rows = E @ relu(x)   (CSR covers every row -> no memset)
    spmm_csr<<<dim3(M_SUB / 8, T_SLICES), 256>>>(
        rpE, colE, valE, M_SUB, NNZ_E,
        out_items, (size_t)N_SUB * H,
        out + (size_t)USER_NUM * H, (size_t)M_SUB * H, 0);
}